// round 12
// baseline (speedup 1.0000x reference)
#include <cuda_runtime.h>
#include <cuda_bf16.h>
#include <cstdint>

// Problem constants (from reference)
#define BATCH 512
#define CH    12
#define TLEN  4096
#define TD    1024     // TLEN / 4 (downsampled)
#define KS    51
#define STEPS 7
#define NTHR  256
#define ROWN  (CH * TLEN)          // 49152 floats per row

// ---------------------------------------------------------------------------
// Fully fused per-row kernel: one CTA owns one batch row.
//   phase A: L2-prefetch of this row's source (overlaps phase B)
//   phase B: downsample + VecInt(7) + polyphase 15-tap conv  -> smem flow
//   phase C: direct-global gather warp (R7 layout: lane == t), store out
// __launch_bounds__(256, 6): cap registers so 6 CTAs/SM stay resident and
// phase C runs at the standalone-k_warp occupancy (R10 failed at 95 regs).
// ---------------------------------------------------------------------------
__global__ __launch_bounds__(NTHR, 6)
void k_fused(const float* __restrict__ src,
             const float* __restrict__ noise,
             const float* __restrict__ flow_mag,
             const float* __restrict__ sker,
             float* __restrict__ out) {
    __shared__ float buf[2][TD];                 // integration ping-pong
    __shared__ float vec_pad[1044];              // [8 z][4*vec 1024][9 z]
    __shared__ float flow_s[TLEN];               // smoothed full-res flow
    __shared__ float ker_s[52];
    __shared__ __align__(16) float h4_s[16 * 4]; // h4_s[k*4+r] = h[r][k-7]

    const int b   = blockIdx.x;
    const int tid = threadIdx.x;
    const float mag = flow_mag[0];
    const float INV_TD1 = 1.0f / (float)(TD - 1);

    const float* srow = src + (size_t)b * ROWN;

    // ---- A. L2 prefetch of the whole source row (1536 lines, 6 per thread)
    {
        const char* base = (const char*)srow;
        #pragma unroll
        for (int k = 0; k < 6; ++k) {
            const char* p = base + (tid + NTHR * k) * 128;
            asm volatile("prefetch.global.L2 [%0];" :: "l"(p));
        }
    }

    // ---- B1. init: resize_linear(flow_field, 0.25) -> src = 4q+1.5,
    //          i0 = 4q+1, w = 0.5 ; resize_transform(<1): *0.25 ; VecInt /2^7
    float f[4];
    {
        const float* nrow = noise + (size_t)b * TLEN;
        #pragma unroll
        for (int j = 0; j < 4; ++j) {
            int q = tid + NTHR * j;
            float n0 = nrow[4 * q + 1];
            float n1 = nrow[4 * q + 2];
            float pf = 0.25f * ((mag * n0) * 0.5f + (mag * n1) * 0.5f);
            f[j] = pf * (1.0f / 128.0f);
            buf[0][q] = f[j];
        }
    }
    if (tid < 51) ker_s[tid] = sker[tid];
    if (tid < 8)  vec_pad[tid] = 0.0f;
    if (tid < 9)  vec_pad[1032 + tid] = 0.0f;
    __syncthreads();

    // ---- B2. composite polyphase kernel h[r][m], m = k-7 in [-7,8]
    //          flow[4q+r] = sum_m h[r][m] * (4*vec[q+m])   (interior)
    if (tid < 64) {
        const int r = tid >> 4;
        const int k = tid & 15;
        const int m = k - 7;
        const float W[4] = {0.625f, 0.875f, 0.125f, 0.375f};
        float acc = 0.0f;
        for (int j = -25; j <= 25; ++j) {
            int srp = r + j + 100;            // sr + 100, 100 % 4 == 0
            int p   = srp / 4 - 25;           // floor_div(sr, 4)
            int rho = srp & 3;
            int d   = (rho >= 2) ? 0 : -1;
            float w = W[rho];
            float g = ker_s[j + 25];
            int tgt = p + d;
            if (tgt == m)     acc += g * (1.0f - w);
            if (tgt + 1 == m) acc += g * w;
        }
        h4_s[k * 4 + r] = acc;
    }
    __syncthreads();

    // ---- B3. VecInt: 7 scaling-and-squaring warp steps.
    // Interior fast path: |field| <= 1.4 (downsampled units) so for
    // y0i in [0, TD-2] the reference's xw/masks/clamps are all exactly 1 /
    // no-ops; dropping x1.0f multiplies is bit-identical. Edge lanes
    // (q in {0,1,1022,1023} only) take the full reference path.
    int cur = 0;
    #pragma unroll
    for (int it = 0; it < STEPS; ++it) {
        const float* bc = buf[cur];
        float* bn = buf[1 - cur];
        #pragma unroll
        for (int j = 0; j < 4; ++j) {
            int q = tid + NTHR * j;
            float nl = (float)q + f[j];
            float y0 = floorf(nl);
            float fy = nl - y0;
            int y0i = (int)y0;
            float warped;
            if (y0i >= 0 && y0i < TD - 1) {
                float g0 = bc[y0i];
                float g1 = bc[y0i + 1];
                warped = (1.0f - fy) * g0 + fy * g1;
            } else {
                float ixn = nl * INV_TD1;
                float xw = fminf(fminf(ixn + 1.0f, 2.0f - ixn), 1.0f);
                xw = fmaxf(xw, 0.0f);
                int y1i = y0i + 1;
                float m0 = (y0i >= 0 && y0i < TD) ? 1.0f : 0.0f;
                float m1 = (y1i >= 0 && y1i < TD) ? 1.0f : 0.0f;
                int y0c = min(max(y0i, 0), TD - 1);
                int y1c = min(max(y1i, 0), TD - 1);
                float g0 = bc[y0c];
                float g1 = bc[y1c];
                warped = xw * ((1.0f - fy) * (m0 * g0) + fy * (m1 * g1));
            }
            f[j] = f[j] + warped;
            bn[q] = f[j];
        }
        cur ^= 1;
        __syncthreads();
    }

    // ---- B4. publish scaled field (resize_transform >1: magnitude x4)
    #pragma unroll
    for (int j = 0; j < 4; ++j)
        vec_pad[8 + tid + NTHR * j] = 4.0f * f[j];
    __syncthreads();

    // ---- B5. 15-tap polyphase conv -> flow_s (full-res smoothed flow)
    {
        const float4* h4 = reinterpret_cast<const float4*>(h4_s);
        float v0 = vec_pad[8];
        float vL = vec_pad[8 + 1023];
        #pragma unroll
        for (int j = 0; j < 4; ++j) {
            int q = tid + NTHR * j;
            const float* wnd = vec_pad + q + 1;  // vec[q-7..q+8] (zero-padded)
            float a0 = 0.f, a1 = 0.f, a2 = 0.f, a3 = 0.f;
            #pragma unroll
            for (int k = 0; k < 16; ++k) {
                float wv = wnd[k];
                float4 hk = h4[k];
                a0 += hk.x * wv;
                a1 += hk.y * wv;
                a2 += hk.z * wv;
                a3 += hk.w * wv;
            }
            // Boundary corrections (R7 derivation): polyphase interior formula
            // with zero-padded vec differs from the reference's clamped
            // upsample + zero-padded conv at exactly 8 upsampled sites.
            if (q < 7 || q >= 1017) {
                auto G = [&](int jj) -> float {
                    return (jj >= -25 && jj <= 25) ? ker_s[jj + 25] : 0.0f;
                };
                auto corr = [&](int tt) -> float {
                    return v0 * (0.375f * (G(-tt)      - G(-1 - tt))
                               + 0.125f * (G(1 - tt)   - G(-2 - tt)))
                         + vL * (0.125f * G(4094 - tt) + 0.375f * G(4095 - tt)
                               - 0.375f * G(4096 - tt) - 0.125f * G(4097 - tt));
                };
                int tt = 4 * q;
                a0 += corr(tt);
                a1 += corr(tt + 1);
                a2 += corr(tt + 2);
                a3 += corr(tt + 3);
            }
            reinterpret_cast<float4*>(flow_s)[q] = make_float4(a0, a1, a2, a3);
        }
    }
    __syncthreads();

    // ---- C. warp-gather this row directly from global (R7 layout: lane==t)
    float* ob_base = out + (size_t)b * ROWN;
    #pragma unroll 2
    for (int w = 0; w < TLEN / NTHR; ++w) {
        int t = tid + NTHR * w;
        float fl = flow_s[t];

        // exact reference fp coordinate sequence
        float nl = (float)t + fl;
        float v  = 2.0f * (nl / (float)(TLEN - 1) - 0.5f);
        float ix = (v + 1.0f) * 0.5f;
        float iy = (v + 1.0f) * 0.5f * (float)(TLEN - 1);

        float xw = fminf(fminf(ix + 1.0f, 2.0f - ix), 1.0f);
        xw = fmaxf(xw, 0.0f);

        float y0 = floorf(iy);
        float fy = iy - y0;
        int y0i = (int)y0;
        int y1i = y0i + 1;
        float a0 = xw * (1.0f - fy) * ((y0i >= 0 && y0i < TLEN) ? 1.0f : 0.0f);
        float a1 = xw * fy         * ((y1i >= 0 && y1i < TLEN) ? 1.0f : 0.0f);
        int y0c = min(max(y0i, 0), TLEN - 1);
        int y1c = min(max(y1i, 0), TLEN - 1);

        // batch all gathers first for maximum MLP, then compute + store
        float g0v[CH], g1v[CH];
        #pragma unroll
        for (int c = 0; c < CH; ++c) {
            const float* sc = srow + c * TLEN;
            g0v[c] = __ldg(sc + y0c);
            g1v[c] = __ldg(sc + y1c);
        }
        float* ob = ob_base + t;
        #pragma unroll
        for (int c = 0; c < CH; ++c) {
            ob[c * TLEN] = a0 * g0v[c] + a1 * g1v[c];
        }
    }
}

// ---------------------------------------------------------------------------
extern "C" void kernel_launch(void* const* d_in, const int* in_sizes, int n_in,
                              void* d_out, int out_size) {
    const float* source    = (const float*)d_in[0];  // [512,12,4096]
    const float* flow_mag  = (const float*)d_in[1];  // [1]
    const float* noise     = (const float*)d_in[2];  // [512,1,4096]
    const float* smooth_k  = (const float*)d_in[3];  // [51]
    float*       out       = (float*)d_out;          // [512,12,4096]

    k_fused<<<BATCH, NTHR>>>(source, noise, flow_mag, smooth_k, out);
}

// round 13
// speedup vs baseline: 1.3846x; 1.3846x over previous
#include <cuda_runtime.h>
#include <cuda_bf16.h>
#include <cstdint>

// Problem constants (from reference)
#define BATCH 512
#define CH    12
#define TLEN  4096
#define TD    1024     // TLEN / 4 (downsampled)
#define KS    51
#define STEPS 7

#define QCH   256      // downsampled chunk per CTA
#define HALO  22       // 7 steps x (+-2) + conv (-7/+8)
#define NEXT  (QCH + 2 * HALO)   // 300 max local elements

// Scratch (static device global; no allocation)
__device__ float g_flow[BATCH * TLEN];  // smoothed full-res flow

// ---------------------------------------------------------------------------
// Halo-split flow kernel: 2048 CTAs (4 chunks/row x 512 rows), each computes
// downsample + VecInt(7) + polyphase conv for its 256-element chunk using a
// 22-element halo -- no inter-CTA communication, 7 local barrier phases only.
// ---------------------------------------------------------------------------
__global__ __launch_bounds__(256) void k_flow(const float* __restrict__ noise,
                                              const float* __restrict__ flow_mag,
                                              const float* __restrict__ sker) {
    __shared__ float buf[2][NEXT + 4];
    __shared__ float vec_pad[8 + NEXT + 9];      // zero pads both ends
    __shared__ float ker_s[52];
    __shared__ __align__(16) float h4_s[16 * 4]; // h4_s[k*4+r] = h[r][k-7]

    const int bid = blockIdx.x;
    const int b   = bid >> 2;          // batch row
    const int ch  = bid & 3;           // chunk in row
    const int c0  = ch * QCH;          // chunk start (downsampled)
    const int lo  = max(0, c0 - HALO);
    const int hi  = min(TD, c0 + QCH + HALO);
    const int n   = hi - lo;           // local element count (<= 300)

    const int tid = threadIdx.x;
    const float mag = flow_mag[0];
    const float INV_TD1 = 1.0f / (float)(TD - 1);

    // ---- init: resize_linear(flow_field, 0.25) -> src = 4q+1.5, i0 = 4q+1,
    //      w = 0.5 ; resize_transform(<1): *0.25 ; VecInt /2^7
    float f0 = 0.0f, f1 = 0.0f;
    {
        const float* nrow = noise + (size_t)b * TLEN;
        {
            int q = lo + tid;
            if (tid < n) {
                float n0 = nrow[4 * q + 1];
                float n1 = nrow[4 * q + 2];
                float pf = 0.25f * ((mag * n0) * 0.5f + (mag * n1) * 0.5f);
                f0 = pf * (1.0f / 128.0f);
                buf[0][tid] = f0;
            }
        }
        {
            int le = tid + 256;
            int q = lo + le;
            if (le < n) {
                float n0 = nrow[4 * q + 1];
                float n1 = nrow[4 * q + 2];
                float pf = 0.25f * ((mag * n0) * 0.5f + (mag * n1) * 0.5f);
                f1 = pf * (1.0f / 128.0f);
                buf[0][le] = f1;
            }
        }
    }
    if (tid < 51) ker_s[tid] = sker[tid];
    if (tid < 8)  vec_pad[tid] = 0.0f;
    if (tid < 9)  vec_pad[8 + n + tid] = 0.0f;
    __syncthreads();

    // ---- composite polyphase kernel h[r][m], m = k-7 in [-7,8]
    //      flow[4q+r] = sum_m h[r][m] * (4*vec[q+m])   (interior)
    if (tid < 64) {
        const int r = tid >> 4;
        const int k = tid & 15;
        const int m = k - 7;
        const float W[4] = {0.625f, 0.875f, 0.125f, 0.375f};
        float acc = 0.0f;
        for (int j = -25; j <= 25; ++j) {
            int srp = r + j + 100;            // sr + 100, 100 % 4 == 0
            int p   = srp / 4 - 25;           // floor_div(sr, 4)
            int rho = srp & 3;
            int d   = (rho >= 2) ? 0 : -1;
            float w = W[rho];
            float g = ker_s[j + 25];
            int tgt = p + d;
            if (tgt == m)     acc += g * (1.0f - w);
            if (tgt + 1 == m) acc += g * w;
        }
        h4_s[k * 4 + r] = acc;
    }
    __syncthreads();

    // ---- VecInt: 7 scaling-and-squaring steps, local halo-shrinking.
    // Interior fast path: for y0i in [0, TD-2] the reference's xw/masks/
    // clamps are exactly 1 / no-ops (|field| <= 1.4), so dropping them is
    // bit-identical. Global-edge lanes take the full reference path.
    // Halo-invalid lanes compute garbage on clamped local reads (never used).
    int cur = 0;
    #pragma unroll
    for (int it = 0; it < STEPS; ++it) {
        const float* bc = buf[cur];
        float* bn = buf[1 - cur];
        #pragma unroll
        for (int j = 0; j < 2; ++j) {
            int le = tid + 256 * j;
            if (le < n) {
                float fv = j ? f1 : f0;
                int q = lo + le;
                float nl = (float)q + fv;
                float y0 = floorf(nl);
                float fy = nl - y0;
                int y0i = (int)y0;
                float warped;
                if (y0i >= 0 && y0i < TD - 1) {
                    int l0 = min(max(y0i - lo, 0), n - 2);  // smem-safety clamp
                    float g0 = bc[l0];
                    float g1 = bc[l0 + 1];
                    warped = (1.0f - fy) * g0 + fy * g1;
                } else {
                    float ixn = nl * INV_TD1;
                    float xw = fminf(fminf(ixn + 1.0f, 2.0f - ixn), 1.0f);
                    xw = fmaxf(xw, 0.0f);
                    int y1i = y0i + 1;
                    float m0 = (y0i >= 0 && y0i < TD) ? 1.0f : 0.0f;
                    float m1 = (y1i >= 0 && y1i < TD) ? 1.0f : 0.0f;
                    int y0c = min(max(y0i, 0), TD - 1);
                    int y1c = min(max(y1i, 0), TD - 1);
                    int l0 = min(max(y0c - lo, 0), n - 1);
                    int l1 = min(max(y1c - lo, 0), n - 1);
                    float g0 = bc[l0];
                    float g1 = bc[l1];
                    warped = xw * ((1.0f - fy) * (m0 * g0) + fy * (m1 * g1));
                }
                fv = fv + warped;
                if (j) f1 = fv; else f0 = fv;
                bn[le] = fv;
            }
        }
        cur ^= 1;
        __syncthreads();
    }

    // ---- publish scaled field (resize_transform >1: magnitude x4)
    if (tid < n)       vec_pad[8 + tid] = 4.0f * f0;
    if (tid + 256 < n) vec_pad[8 + tid + 256] = 4.0f * f1;
    __syncthreads();

    // ---- 15-tap polyphase conv: thread tid emits flow[4q .. 4q+3], q=c0+tid
    {
        const int q = c0 + tid;
        const float4* h4 = reinterpret_cast<const float4*>(h4_s);
        // window vec[q-7 .. q+8]; padded-zero array handles global ends
        const float* wnd = vec_pad + (q - lo) + 1;
        float a0 = 0.f, a1 = 0.f, a2 = 0.f, a3 = 0.f;
        #pragma unroll
        for (int k = 0; k < 16; ++k) {
            float wv = wnd[k];
            float4 hk = h4[k];
            a0 += hk.x * wv;
            a1 += hk.y * wv;
            a2 += hk.z * wv;
            a3 += hk.w * wv;
        }

        // Boundary corrections (R7 derivation): polyphase interior formula
        // with zero-padded vec differs from the reference's clamped upsample
        // + zero-padded conv at exactly 8 upsampled sites; only outputs near
        // row ends are affected (chunk 0 uses v0, chunk 3 uses vL; the other
        // term's kernel arguments are out of range -> exactly 0).
        if (q < 7 || q >= 1017) {
            float v0 = (c0 == 0)  ? vec_pad[8]                 : 0.0f;
            float vL = (hi == TD) ? vec_pad[8 + (1023 - lo)]   : 0.0f;
            auto G = [&](int jj) -> float {
                return (jj >= -25 && jj <= 25) ? ker_s[jj + 25] : 0.0f;
            };
            auto corr = [&](int tt) -> float {
                return v0 * (0.375f * (G(-tt)      - G(-1 - tt))
                           + 0.125f * (G(1 - tt)   - G(-2 - tt)))
                     + vL * (0.125f * G(4094 - tt) + 0.375f * G(4095 - tt)
                           - 0.375f * G(4096 - tt) - 0.125f * G(4097 - tt));
            };
            int tt = 4 * q;
            a0 += corr(tt);
            a1 += corr(tt + 1);
            a2 += corr(tt + 2);
            a3 += corr(tt + 3);
        }

        reinterpret_cast<float4*>(g_flow + (size_t)b * TLEN)[q] =
            make_float4(a0, a1, a2, a3);
    }
}

// ---------------------------------------------------------------------------
// Final warp of source by smoothed flow (verbatim R7 kernel: 33.2 us,
// DRAM 61%, within ~5% of the compulsory-traffic floor). Thread per (b,t);
// consecutive lanes on consecutive t; all 12 channels per thread.
// ---------------------------------------------------------------------------
__global__ __launch_bounds__(256) void k_warp(const float* __restrict__ src,
                                              float* __restrict__ out) {
    int idx = blockIdx.x * 256 + threadIdx.x;   // over BATCH*TLEN
    int b = idx >> 12;
    int t = idx & (TLEN - 1);

    float f  = g_flow[idx];
    float nl = (float)t + f;
    float v  = 2.0f * (nl / (float)(TLEN - 1) - 0.5f);
    float ix = (v + 1.0f) * 0.5f;
    float iy = (v + 1.0f) * 0.5f * (float)(TLEN - 1);

    float xw = fminf(fminf(ix + 1.0f, 2.0f - ix), 1.0f);
    xw = fmaxf(xw, 0.0f);

    float y0 = floorf(iy);
    float fy = iy - y0;
    int y0i = (int)y0;
    int y1i = y0i + 1;
    float a0 = xw * (1.0f - fy) * ((y0i >= 0 && y0i < TLEN) ? 1.0f : 0.0f);
    float a1 = xw * fy         * ((y1i >= 0 && y1i < TLEN) ? 1.0f : 0.0f);
    int y0c = min(max(y0i, 0), TLEN - 1);
    int y1c = min(max(y1i, 0), TLEN - 1);

    const float* sb = src + (size_t)b * (CH * TLEN);
    float*       ob = out + (size_t)b * (CH * TLEN) + t;

    // Batch all gather loads first for maximum MLP, then compute + store.
    float g0v[CH], g1v[CH];
    #pragma unroll
    for (int c = 0; c < CH; ++c) {
        const float* sc = sb + c * TLEN;
        g0v[c] = __ldg(sc + y0c);
        g1v[c] = __ldg(sc + y1c);
    }
    #pragma unroll
    for (int c = 0; c < CH; ++c) {
        ob[c * TLEN] = a0 * g0v[c] + a1 * g1v[c];
    }
}

// ---------------------------------------------------------------------------
extern "C" void kernel_launch(void* const* d_in, const int* in_sizes, int n_in,
                              void* d_out, int out_size) {
    const float* source    = (const float*)d_in[0];  // [512,12,4096]
    const float* flow_mag  = (const float*)d_in[1];  // [1]
    const float* noise     = (const float*)d_in[2];  // [512,1,4096]
    const float* smooth_k  = (const float*)d_in[3];  // [51]
    float*       out       = (float*)d_out;          // [512,12,4096]

    k_flow<<<BATCH * 4, 256>>>(noise, flow_mag, smooth_k);
    k_warp<<<(BATCH * TLEN) / 256, 256>>>(source, out);
}

// round 14
// speedup vs baseline: 1.5652x; 1.1304x over previous
#include <cuda_runtime.h>
#include <cuda_bf16.h>
#include <cstdint>

// Problem constants (from reference)
#define BATCH 512
#define CH    12
#define TLEN  4096
#define TD    1024     // TLEN / 4 (downsampled)
#define KS    51
#define STEPS 7

// Scratch (static device globals; no allocation)
__device__ float g_vec[BATCH * TD];   // integrated, x4-scaled downsampled field
__device__ float g_h4[64];            // polyphase table h4[k*4+r], k=0..15

// ---------------------------------------------------------------------------
// Flow kernel (R8 structure, conv removed): downsample + VecInt(7) with the
// measured-best branchless mask formula; 256 thr, 4 elems/thread strided.
// Writes the x4-scaled field to g_vec (2 MB). Block 0 also emits g_h4.
// ---------------------------------------------------------------------------
__global__ __launch_bounds__(256) void k_flow(const float* __restrict__ noise,
                                              const float* __restrict__ flow_mag,
                                              const float* __restrict__ sker) {
    __shared__ float buf[2][TD];
    __shared__ float ker_s[52];

    const int b   = blockIdx.x;
    const int tid = threadIdx.x;
    const float mag = flow_mag[0];
    const float INV_TD1 = 1.0f / (float)(TD - 1);

    // ---- init: resize_linear(flow_field, 0.25) -> src = 4q+1.5, i0 = 4q+1,
    //      w = 0.5 ; resize_transform(<1): *0.25 ; VecInt /2^7
    float f[4];
    {
        const float* nrow = noise + (size_t)b * TLEN;
        #pragma unroll
        for (int j = 0; j < 4; ++j) {
            int q = tid + 256 * j;
            float n0 = nrow[4 * q + 1];
            float n1 = nrow[4 * q + 2];
            float pf = 0.25f * ((mag * n0) * 0.5f + (mag * n1) * 0.5f);
            f[j] = pf * (1.0f / 128.0f);
            buf[0][q] = f[j];
        }
    }
    if (tid < 51) ker_s[tid] = sker[tid];
    __syncthreads();

    // ---- block 0: composite polyphase kernel h[r][m], m = k-7 in [-7,8]
    //      flow[4q+r] = sum_m h[r][m] * (4*vec[q+m])   (interior)
    if (b == 0 && tid < 64) {
        const int r = tid >> 4;
        const int k = tid & 15;
        const int m = k - 7;
        const float W[4] = {0.625f, 0.875f, 0.125f, 0.375f};
        float acc = 0.0f;
        for (int j = -25; j <= 25; ++j) {
            int srp = r + j + 100;            // sr + 100, 100 % 4 == 0
            int p   = srp / 4 - 25;           // floor_div(sr, 4)
            int rho = srp & 3;
            int d   = (rho >= 2) ? 0 : -1;
            float w = W[rho];
            float g = ker_s[j + 25];
            int tgt = p + d;
            if (tgt == m)     acc += g * (1.0f - w);
            if (tgt + 1 == m) acc += g * w;
        }
        g_h4[k * 4 + r] = acc;
    }

    // ---- VecInt: 7 scaling-and-squaring steps (branchless mask formula —
    //      the measured-best R8 sequence, bit-exact vs reference)
    int cur = 0;
    #pragma unroll
    for (int it = 0; it < STEPS; ++it) {
        const float* bc = buf[cur];
        float* bn = buf[1 - cur];
        #pragma unroll
        for (int j = 0; j < 4; ++j) {
            int q = tid + 256 * j;
            float nl = (float)q + f[j];

            float ixn = nl * INV_TD1;
            float xw = fminf(fminf(ixn + 1.0f, 2.0f - ixn), 1.0f);
            xw = fmaxf(xw, 0.0f);

            float y0 = floorf(nl);
            float fy = nl - y0;
            int y0i = (int)y0;
            int y1i = y0i + 1;
            float m0 = (y0i >= 0 && y0i < TD) ? 1.0f : 0.0f;
            float m1 = (y1i >= 0 && y1i < TD) ? 1.0f : 0.0f;
            int y0c = min(max(y0i, 0), TD - 1);
            int y1c = min(max(y1i, 0), TD - 1);
            float g0 = bc[y0c];
            float g1 = bc[y1c];
            float warped = xw * ((1.0f - fy) * (m0 * g0) + fy * (m1 * g1));
            f[j] = f[j] + warped;
            bn[q] = f[j];
        }
        cur ^= 1;
        __syncthreads();
    }

    // ---- publish x4-scaled field (resize_transform >1: magnitude x4)
    float* vrow = g_vec + (size_t)b * TD;
    #pragma unroll
    for (int j = 0; j < 4; ++j)
        vrow[tid + 256 * j] = 4.0f * f[j];
}

// ---------------------------------------------------------------------------
// Warp kernel (R7 layout) + in-place polyphase conv. Each CTA covers 256
// consecutive t of one row: stage the 79-float vec window + h4 table in smem,
// each thread evaluates its 16-tap phase sum (identical FMA order to the
// R8 conv -> bit-identical flow), then gathers/stores all 12 channels.
// ---------------------------------------------------------------------------
__global__ __launch_bounds__(256) void k_warp(const float* __restrict__ src,
                                              const float* __restrict__ sker,
                                              float* __restrict__ out) {
    __shared__ float win[80];     // vec[qbase-7 .. qbase+71], zero-padded
    __shared__ float h4_s[64];

    const int tid = threadIdx.x;
    const int blk = blockIdx.x;            // over (BATCH*TLEN)/256
    const int b   = blk >> 4;              // 16 chunks per row
    const int t0  = (blk & 15) << 8;       // chunk start (t)
    const int qb  = t0 >> 2;               // chunk start (q)
    const int t   = t0 + tid;

    const float* vrow = g_vec + (size_t)b * TD;
    if (tid < 64) h4_s[tid] = g_h4[tid];
    if (tid < 79) {
        int q = qb - 7 + tid;
        win[tid] = (q >= 0 && q < TD) ? __ldg(vrow + q) : 0.0f;
    }
    __syncthreads();

    // ---- polyphase conv for this t: r = t&3, window base = tid>>2
    float fl;
    {
        const int r  = tid & 3;
        const int wb = tid >> 2;
        float acc = 0.0f;
        #pragma unroll
        for (int k = 0; k < 16; ++k)
            acc += h4_s[k * 4 + r] * win[wb + k];

        // Boundary corrections (R7 derivation): only t<28 or t>=4068.
        if (t < 28 || t >= 4068) {
            float v0 = __ldg(vrow);
            float vL = __ldg(vrow + (TD - 1));
            auto G = [&](int jj) -> float {
                return (jj >= -25 && jj <= 25) ? __ldg(sker + jj + 25) : 0.0f;
            };
            acc += v0 * (0.375f * (G(-t)      - G(-1 - t))
                       + 0.125f * (G(1 - t)   - G(-2 - t)))
                 + vL * (0.125f * G(4094 - t) + 0.375f * G(4095 - t)
                       - 0.375f * G(4096 - t) - 0.125f * G(4097 - t));
        }
        fl = acc;
    }

    // ---- exact reference fp coordinate sequence
    float nl = (float)t + fl;
    float v  = 2.0f * (nl / (float)(TLEN - 1) - 0.5f);
    float ix = (v + 1.0f) * 0.5f;
    float iy = (v + 1.0f) * 0.5f * (float)(TLEN - 1);

    float xw = fminf(fminf(ix + 1.0f, 2.0f - ix), 1.0f);
    xw = fmaxf(xw, 0.0f);

    float y0 = floorf(iy);
    float fy = iy - y0;
    int y0i = (int)y0;
    int y1i = y0i + 1;
    float a0 = xw * (1.0f - fy) * ((y0i >= 0 && y0i < TLEN) ? 1.0f : 0.0f);
    float a1 = xw * fy         * ((y1i >= 0 && y1i < TLEN) ? 1.0f : 0.0f);
    int y0c = min(max(y0i, 0), TLEN - 1);
    int y1c = min(max(y1i, 0), TLEN - 1);

    const float* sb = src + (size_t)b * (CH * TLEN);
    float*       ob = out + (size_t)b * (CH * TLEN) + t;

    // Batch all gather loads first for maximum MLP, then compute + store.
    float g0v[CH], g1v[CH];
    #pragma unroll
    for (int c = 0; c < CH; ++c) {
        const float* sc = sb + c * TLEN;
        g0v[c] = __ldg(sc + y0c);
        g1v[c] = __ldg(sc + y1c);
    }
    #pragma unroll
    for (int c = 0; c < CH; ++c) {
        ob[c * TLEN] = a0 * g0v[c] + a1 * g1v[c];
    }
}

// ---------------------------------------------------------------------------
extern "C" void kernel_launch(void* const* d_in, const int* in_sizes, int n_in,
                              void* d_out, int out_size) {
    const float* source    = (const float*)d_in[0];  // [512,12,4096]
    const float* flow_mag  = (const float*)d_in[1];  // [1]
    const float* noise     = (const float*)d_in[2];  // [512,1,4096]
    const float* smooth_k  = (const float*)d_in[3];  // [51]
    float*       out       = (float*)d_out;          // [512,12,4096]

    k_flow<<<BATCH, 256>>>(noise, flow_mag, smooth_k);
    k_warp<<<(BATCH * TLEN) / 256, 256>>>(source, smooth_k, out);
}

// round 15
// speedup vs baseline: 1.7143x; 1.0952x over previous
#include <cuda_runtime.h>
#include <cuda_bf16.h>
#include <cstdint>

// Problem constants (from reference)
#define BATCH 512
#define CH    12
#define TLEN  4096
#define TD    1024     // TLEN / 4 (downsampled)
#define KS    51
#define STEPS 7

// Scratch (static device globals; no allocation)
__device__ float g_vec[BATCH * TD];   // integrated, x4-scaled downsampled field
__device__ float g_h4[64];            // polyphase table h4[k*4+r], k=0..15

// ---------------------------------------------------------------------------
// Flow kernel: downsample + VecInt(7), branchless mask formula (bit-exact vs
// reference). 1024 threads, 1 elem/thread: 2 CTAs/SM = 2048 resident threads
// hide the 7 serial barrier phases (R4-measured best shape for this loop).
// Writes the x4-scaled field to g_vec (2 MB). Block 0 also emits g_h4.
// ---------------------------------------------------------------------------
__global__ __launch_bounds__(1024) void k_flow(const float* __restrict__ noise,
                                               const float* __restrict__ flow_mag,
                                               const float* __restrict__ sker) {
    __shared__ float buf[2][TD];
    __shared__ float ker_s[52];

    const int b = blockIdx.x;
    const int q = threadIdx.x;
    const float mag = flow_mag[0];
    const float INV_TD1 = 1.0f / (float)(TD - 1);

    // ---- init: resize_linear(flow_field, 0.25) -> src = 4q+1.5, i0 = 4q+1,
    //      w = 0.5 ; resize_transform(<1): *0.25 ; VecInt /2^7
    float f;
    {
        const float* nrow = noise + (size_t)b * TLEN;
        float n0 = nrow[4 * q + 1];
        float n1 = nrow[4 * q + 2];
        float pf = 0.25f * ((mag * n0) * 0.5f + (mag * n1) * 0.5f);
        f = pf * (1.0f / 128.0f);
        buf[0][q] = f;
    }
    if (q < 51) ker_s[q] = sker[q];
    __syncthreads();

    // ---- block 0: composite polyphase kernel h[r][m], m = k-7 in [-7,8]
    //      flow[4p+r] = sum_m h[r][m] * (4*vec[p+m])   (interior)
    if (b == 0 && q < 64) {
        const int r = q >> 4;
        const int k = q & 15;
        const int m = k - 7;
        const float W[4] = {0.625f, 0.875f, 0.125f, 0.375f};
        float acc = 0.0f;
        for (int j = -25; j <= 25; ++j) {
            int srp = r + j + 100;            // sr + 100, 100 % 4 == 0
            int p   = srp / 4 - 25;           // floor_div(sr, 4)
            int rho = srp & 3;
            int d   = (rho >= 2) ? 0 : -1;
            float w = W[rho];
            float g = ker_s[j + 25];
            int tgt = p + d;
            if (tgt == m)     acc += g * (1.0f - w);
            if (tgt + 1 == m) acc += g * w;
        }
        g_h4[k * 4 + r] = acc;
    }

    // ---- VecInt: 7 scaling-and-squaring steps (branchless, bit-exact)
    int cur = 0;
    #pragma unroll
    for (int it = 0; it < STEPS; ++it) {
        const float* bc = buf[cur];
        float nl = (float)q + f;

        float ixn = nl * INV_TD1;
        float xw = fminf(fminf(ixn + 1.0f, 2.0f - ixn), 1.0f);
        xw = fmaxf(xw, 0.0f);

        float y0 = floorf(nl);
        float fy = nl - y0;
        int y0i = (int)y0;
        int y1i = y0i + 1;
        float m0 = (y0i >= 0 && y0i < TD) ? 1.0f : 0.0f;
        float m1 = (y1i >= 0 && y1i < TD) ? 1.0f : 0.0f;
        int y0c = min(max(y0i, 0), TD - 1);
        int y1c = min(max(y1i, 0), TD - 1);
        float g0 = bc[y0c];
        float g1 = bc[y1c];
        float warped = xw * ((1.0f - fy) * (m0 * g0) + fy * (m1 * g1));
        f = f + warped;
        buf[1 - cur][q] = f;
        cur ^= 1;
        __syncthreads();
    }

    // ---- publish x4-scaled field (resize_transform >1: magnitude x4)
    g_vec[(size_t)b * TD + q] = 4.0f * f;
}

// ---------------------------------------------------------------------------
// Warp kernel (R7 layout) + in-place polyphase conv. Each CTA covers 256
// consecutive t of one row: stage the 79-float vec window + h4 table in smem,
// evaluate the 16-tap phase sum (identical FMA order -> bit-identical flow),
// then gather/store all 12 channels. L2-prefetch of the gather lines is
// issued BEFORE the conv so its latency overlaps DRAM streaming.
// ---------------------------------------------------------------------------
__global__ __launch_bounds__(256) void k_warp(const float* __restrict__ src,
                                              const float* __restrict__ sker,
                                              float* __restrict__ out) {
    __shared__ float win[80];     // vec[qbase-7 .. qbase+71], zero-padded
    __shared__ float h4_s[64];

    const int tid = threadIdx.x;
    const int blk = blockIdx.x;            // over (BATCH*TLEN)/256
    const int b   = blk >> 4;              // 16 chunks per row
    const int t0  = (blk & 15) << 8;       // chunk start (t)
    const int qb  = t0 >> 2;               // chunk start (q)
    const int t   = t0 + tid;

    const float* sb = src + (size_t)b * (CH * TLEN);

    // ---- prefetch the gather lines (targets provably within t +- 6.5, i.e.
    //      the 128B line holding index t, occasionally its neighbor) so the
    //      conv below overlaps the DRAM stream instead of stalling it.
    {
        #pragma unroll
        for (int c = 0; c < CH; ++c) {
            const char* p = (const char*)(sb + c * TLEN + t);
            asm volatile("prefetch.global.L2 [%0];" :: "l"(p));
        }
    }

    const float* vrow = g_vec + (size_t)b * TD;
    if (tid < 64) h4_s[tid] = g_h4[tid];
    if (tid < 79) {
        int q = qb - 7 + tid;
        win[tid] = (q >= 0 && q < TD) ? __ldg(vrow + q) : 0.0f;
    }
    __syncthreads();

    // ---- polyphase conv for this t: r = t&3, window base = tid>>2
    float fl;
    {
        const int r  = tid & 3;
        const int wb = tid >> 2;
        float acc = 0.0f;
        #pragma unroll
        for (int k = 0; k < 16; ++k)
            acc += h4_s[k * 4 + r] * win[wb + k];

        // Boundary corrections (R7 derivation): only t<28 or t>=4068.
        if (t < 28 || t >= 4068) {
            float v0 = __ldg(vrow);
            float vL = __ldg(vrow + (TD - 1));
            auto G = [&](int jj) -> float {
                return (jj >= -25 && jj <= 25) ? __ldg(sker + jj + 25) : 0.0f;
            };
            acc += v0 * (0.375f * (G(-t)      - G(-1 - t))
                       + 0.125f * (G(1 - t)   - G(-2 - t)))
                 + vL * (0.125f * G(4094 - t) + 0.375f * G(4095 - t)
                       - 0.375f * G(4096 - t) - 0.125f * G(4097 - t));
        }
        fl = acc;
    }

    // ---- exact reference fp coordinate sequence
    float nl = (float)t + fl;
    float v  = 2.0f * (nl / (float)(TLEN - 1) - 0.5f);
    float ix = (v + 1.0f) * 0.5f;
    float iy = (v + 1.0f) * 0.5f * (float)(TLEN - 1);

    float xw = fminf(fminf(ix + 1.0f, 2.0f - ix), 1.0f);
    xw = fmaxf(xw, 0.0f);

    float y0 = floorf(iy);
    float fy = iy - y0;
    int y0i = (int)y0;
    int y1i = y0i + 1;
    float a0 = xw * (1.0f - fy) * ((y0i >= 0 && y0i < TLEN) ? 1.0f : 0.0f);
    float a1 = xw * fy         * ((y1i >= 0 && y1i < TLEN) ? 1.0f : 0.0f);
    int y0c = min(max(y0i, 0), TLEN - 1);
    int y1c = min(max(y1i, 0), TLEN - 1);

    float* ob = out + (size_t)b * (CH * TLEN) + t;

    // Batch all gather loads first for maximum MLP, then compute + store.
    float g0v[CH], g1v[CH];
    #pragma unroll
    for (int c = 0; c < CH; ++c) {
        const float* sc = sb + c * TLEN;
        g0v[c] = __ldg(sc + y0c);
        g1v[c] = __ldg(sc + y1c);
    }
    #pragma unroll
    for (int c = 0; c < CH; ++c) {
        ob[c * TLEN] = a0 * g0v[c] + a1 * g1v[c];
    }
}

// ---------------------------------------------------------------------------
extern "C" void kernel_launch(void* const* d_in, const int* in_sizes, int n_in,
                              void* d_out, int out_size) {
    const float* source    = (const float*)d_in[0];  // [512,12,4096]
    const float* flow_mag  = (const float*)d_in[1];  // [1]
    const float* noise     = (const float*)d_in[2];  // [512,1,4096]
    const float* smooth_k  = (const float*)d_in[3];  // [51]
    float*       out       = (float*)d_out;          // [512,12,4096]

    k_flow<<<BATCH, 1024>>>(noise, flow_mag, smooth_k);
    k_warp<<<(BATCH * TLEN) / 256, 256>>>(source, smooth_k, out);
}